// round 14
// baseline (speedup 1.0000x reference)
#include <cuda_runtime.h>
#include <cuda_bf16.h>
#include <math.h>

#define H    16
#define L    2048
#define DK   64
#define RB   32
#define ROWS 16
#define SPAD 20          // padded row of S[j][.] in floats (16 data + 4 pad)

// Scratch (device globals: no allocs allowed)
__device__ float g_C[H * L * RB];
__device__ float g_B[H * L * RB];
__device__ __nv_bfloat16 g_Phi[(size_t)H * L * L];   // bf16 split of P (hi)
__device__ __nv_bfloat16 g_Plo[(size_t)H * L * L];   // bf16 split of P (lo)
__device__ __nv_bfloat16 g_Vthi[(size_t)H * DK * L]; // v transposed [d][j], hi
__device__ __nv_bfloat16 g_Vtlo[(size_t)H * DK * L]; // v transposed [d][j], lo

// ---- f32x2 packed helpers --------------------------------------------------
typedef unsigned long long u64;

__device__ __forceinline__ void fma2(u64 &acc, u64 a, u64 b) {
    asm("fma.rn.f32x2 %0, %1, %2, %0;" : "+l"(acc) : "l"(a), "l"(b));
}
__device__ __forceinline__ float2 upk(u64 v) {
    float2 r; asm("mov.b64 {%0, %1}, %2;" : "=f"(r.x), "=f"(r.y) : "l"(v)); return r;
}
__device__ __forceinline__ void cp16(float* dst_smem, const float* src) {
    unsigned s = (unsigned)__cvta_generic_to_shared(dst_smem);
    asm volatile("cp.async.cg.shared.global [%0], [%1], 16;" :: "r"(s), "l"(src));
}
__device__ __forceinline__ void cp_commit() {
    asm volatile("cp.async.commit_group;");
}
__device__ __forceinline__ void cp_wait0() {
    asm volatile("cp.async.wait_group 0;");
}

#define MMA16816(D, A, B)                                                     \
    asm volatile("mma.sync.aligned.m16n8k16.row.col.f32.bf16.bf16.f32 "       \
                 "{%0,%1,%2,%3}, {%4,%5,%6,%7}, {%8,%9}, {%0,%1,%2,%3};"      \
                 : "+f"((D)[0]), "+f"((D)[1]), "+f"((D)[2]), "+f"((D)[3])     \
                 : "r"((A)[0]), "r"((A)[1]), "r"((A)[2]), "r"((A)[3]),        \
                   "r"((B)[0]), "r"((B)[1]))

// ---------------------------------------------------------------------------
// Kernel 1: projections (unchanged).
// ---------------------------------------------------------------------------
__global__ __launch_bounds__(256)
void proj_kernel(const float* __restrict__ q,
                 const float* __restrict__ Wa, const float* __restrict__ ba,
                 const float* __restrict__ Wb, const float* __restrict__ bb) {
    __shared__ float Ut[DK * DK];   // [k][o]
    __shared__ float us[DK];
    __shared__ float qs[64 * DK];   // [r][k]
    int tid = threadIdx.x;
    int row0 = blockIdx.x * 64;

    for (int i = tid; i < DK * DK; i += 256) {
        int o = i >> 6, k = i & 63;
        float u;
        if (o < 32) u = 32.f * (Wa[(2 * o) * DK + k] + Wa[(2 * o + 1) * DK + k]);
        else        u = Wb[(o - 32) * DK + k];
        Ut[k * DK + o] = u;
    }
    if (tid < DK)
        us[tid] = (tid < 32) ? 32.f * (ba[2 * tid] + ba[2 * tid + 1]) : bb[tid - 32];
    {
        float4* q4 = (float4*)qs;  const float4* g4 = (const float4*)(q + (size_t)row0 * DK);
        for (int i = tid; i < 64 * DK / 4; i += 256) q4[i] = g4[i];
    }
    __syncthreads();

    int tr = tid >> 4, tc = tid & 15;
    float acc[4][4] = {};
#pragma unroll 8
    for (int k = 0; k < DK; k++) {
        float4 u = *(const float4*)(Ut + k * DK + 4 * tc);
        float qv[4];
#pragma unroll
        for (int ri = 0; ri < 4; ri++) qv[ri] = qs[(4 * tr + ri) * DK + k];
#pragma unroll
        for (int ri = 0; ri < 4; ri++) {
            acc[ri][0] += qv[ri] * u.x;  acc[ri][1] += qv[ri] * u.y;
            acc[ri][2] += qv[ri] * u.z;  acc[ri][3] += qv[ri] * u.w;
        }
    }
    float4 ub = *(const float4*)(us + 4 * tc);
#pragma unroll
    for (int ri = 0; ri < 4; ri++) {
        int row = row0 + 4 * tr + ri;
        float4 o = make_float4(acc[ri][0] + ub.x, acc[ri][1] + ub.y,
                               acc[ri][2] + ub.z, acc[ri][3] + ub.w);
        if (tc < 8) *(float4*)(g_C + (size_t)row * RB + 4 * tc)        = o;
        else        *(float4*)(g_B + (size_t)row * RB + (4 * tc - 32)) = o;
    }
}

// ---------------------------------------------------------------------------
// Kernel 2: v transpose + bf16 split.  Vt_hi/lo[head][d][j].
// One CTA per (head, 64-j tile), smem-tiled transpose, coalesced both ways.
// ---------------------------------------------------------------------------
__global__ __launch_bounds__(256)
void vsplit_kernel(const float* __restrict__ v) {
    __shared__ float ts[64][65];
    int tid = threadIdx.x;
    int head = blockIdx.x >> 5;          // L/64 = 32 tiles per head
    int j0 = (blockIdx.x & 31) * 64;
    const float* gv = v + ((size_t)head * L + j0) * DK;
#pragma unroll
    for (int i = tid; i < 64 * 64; i += 256) {
        int jj = i >> 6, d = i & 63;
        ts[jj][d] = gv[jj * DK + d];
    }
    __syncthreads();
#pragma unroll
    for (int i = tid; i < 64 * 64; i += 256) {
        int d = i >> 6, jj = i & 63;
        float val = ts[jj][d];
        __nv_bfloat16 hi = __float2bfloat16(val);
        __nv_bfloat16 lo = __float2bfloat16(val - __bfloat162float(hi));
        size_t idx = ((size_t)head * DK + d) * L + j0 + jj;
        g_Vthi[idx] = hi;
        g_Vtlo[idx] = lo;
    }
}

// ---------------------------------------------------------------------------
// Kernel 3: fused S + softmax (R11 base, Phase 3 removed).
// Phase 2 pass 3 additionally emits bf16 split P_hi/P_lo for the GEMM.
// ---------------------------------------------------------------------------
__global__ __launch_bounds__(512, 1)
void attn_kernel(float* __restrict__ attn) { // [H, L, L]
    extern __shared__ float sm[];
    float* S   = sm;                  // L * SPAD  = 40960 floats
    float* Cs  = S + L * SPAD;        // ROWS * RB = 512
    float* buf = Cs + ROWS * RB;      // 2 x 8192 floats (B double-buffer)

    int tid  = threadIdx.x;
    int lane = tid & 31, w = tid >> 5;
    int head = blockIdx.x >> 7;
    int rt   = blockIdx.x & 127;
    int row0 = rt * ROWS;

    const float* gB = g_B + (size_t)head * L * RB;

    // stage chunk 0
    {
#pragma unroll
        for (int t = 0; t < 4; t++) {
            int idx4 = tid + 512 * t;              // float4 index, 0..2047
            int j = idx4 >> 3, i = idx4 & 7;
            cp16(buf + j * RB + 4 * (i ^ (j & 7)), gB + (size_t)j * RB + 4 * i);
        }
        cp_commit();
    }

    // C tile for these 16 rows
    {
        const float4* c4 = (const float4*)(g_C + (size_t)(head * L + row0) * RB);
        float4* d4 = (float4*)Cs;
        for (int i = tid; i < ROWS * RB / 4; i += 512) d4[i] = c4[i];
    }

    // ---- Phase 1: S[j][r] = sum_m C[r][m] * B[j][m] --------------------------
    int jq = tid & 127, rq = tid >> 7;        // 2 j per thread, 4-row quad rq
    for (int c = 0; c < 8; c++) {
        cp_wait0();
        __syncthreads();
        if (c < 7) {
            float* bn = buf + ((c + 1) & 1) * 8192;
            const float* gn = gB + (size_t)(c + 1) * 256 * RB;
#pragma unroll
            for (int t = 0; t < 4; t++) {
                int idx4 = tid + 512 * t;
                int j = idx4 >> 3, i = idx4 & 7;
                cp16(bn + j * RB + 4 * (i ^ (j & 7)), gn + (size_t)j * RB + 4 * i);
            }
            cp_commit();
        }
        const float* bc = buf + (c & 1) * 8192;
        int j0 = c * 256;
        int jA = jq, jB = jq + 128;
        u64 acc[2][4];
#pragma unroll
        for (int a = 0; a < 2; a++)
#pragma unroll
            for (int b = 0; b < 4; b++) acc[a][b] = 0ull;
#pragma unroll
        for (int i = 0; i < 8; i++) {
            ulonglong2 c0 = *(const ulonglong2*)(Cs + (4 * rq + 0) * RB + 4 * i);
            ulonglong2 c1 = *(const ulonglong2*)(Cs + (4 * rq + 1) * RB + 4 * i);
            ulonglong2 c2 = *(const ulonglong2*)(Cs + (4 * rq + 2) * RB + 4 * i);
            ulonglong2 c3 = *(const ulonglong2*)(Cs + (4 * rq + 3) * RB + 4 * i);
            ulonglong2 bA = *(const ulonglong2*)(bc + jA * RB + 4 * (i ^ (jA & 7)));
            ulonglong2 bB = *(const ulonglong2*)(bc + jB * RB + 4 * (i ^ (jB & 7)));
            fma2(acc[0][0], c0.x, bA.x);  fma2(acc[0][0], c0.y, bA.y);
            fma2(acc[0][1], c1.x, bA.x);  fma2(acc[0][1], c1.y, bA.y);
            fma2(acc[0][2], c2.x, bA.x);  fma2(acc[0][2], c2.y, bA.y);
            fma2(acc[0][3], c3.x, bA.x);  fma2(acc[0][3], c3.y, bA.y);
            fma2(acc[1][0], c0.x, bB.x);  fma2(acc[1][0], c0.y, bB.y);
            fma2(acc[1][1], c1.x, bB.x);  fma2(acc[1][1], c1.y, bB.y);
            fma2(acc[1][2], c2.x, bB.x);  fma2(acc[1][2], c2.y, bB.y);
            fma2(acc[1][3], c3.x, bB.x);  fma2(acc[1][3], c3.y, bB.y);
        }
        {
            float2 t0 = upk(acc[0][0]), t1 = upk(acc[0][1]),
                   t2 = upk(acc[0][2]), t3 = upk(acc[0][3]);
            int key = (jA >> 3) & 1;
            *(float4*)(S + (size_t)(j0 + jA) * SPAD + 4 * (rq ^ key)) =
                make_float4(t0.x + t0.y, t1.x + t1.y, t2.x + t2.y, t3.x + t3.y);
        }
        {
            float2 t0 = upk(acc[1][0]), t1 = upk(acc[1][1]),
                   t2 = upk(acc[1][2]), t3 = upk(acc[1][3]);
            int key = (jB >> 3) & 1;
            *(float4*)(S + (size_t)(j0 + jB) * SPAD + 4 * (rq ^ key)) =
                make_float4(t0.x + t0.y, t1.x + t1.y, t2.x + t2.y, t3.x + t3.y);
        }
    }
    __syncthreads();

    // ---- Phase 2: softmax, warp w owns row w; emit attn + bf16 split --------
    {
        int r = w, g = r >> 2, e = r & 3;
        int off = 4 * (g ^ ((lane >> 3) & 1)) + e;   // per-lane constant slot
        const float* p0 = S + lane * SPAD + off;
        float mx = -1e30f;
#pragma unroll
        for (int k = 0; k < 64; k++) { mx = fmaxf(mx, *p0); p0 += 32 * SPAD; }
#pragma unroll
        for (int o = 16; o > 0; o >>= 1) mx = fmaxf(mx, __shfl_xor_sync(0xffffffffu, mx, o));
        float* p1 = S + lane * SPAD + off;
        float sum = 0.f;
#pragma unroll
        for (int k = 0; k < 64; k++) {
            float ee = __expf(*p1 - mx);
            *p1 = ee;
            sum += ee;
            p1 += 32 * SPAD;
        }
#pragma unroll
        for (int o = 16; o > 0; o >>= 1) sum += __shfl_xor_sync(0xffffffffu, sum, o);
        float inv = 1.f / sum;
        size_t rbase = (size_t)(head * L + row0 + r) * L + lane;
        const float* p2 = S + lane * SPAD + off;
        float* ar = attn + rbase;
        __nv_bfloat16* ph = g_Phi + rbase;
        __nv_bfloat16* pl = g_Plo + rbase;
#pragma unroll
        for (int k = 0; k < 64; k++) {
            float p = *p2 * inv;
            *ar = p;                                   // dense_attn (fp32)
            __nv_bfloat16 hi = __float2bfloat16(p);
            *ph = hi;
            *pl = __float2bfloat16(p - __bfloat162float(hi));
            p2 += 32 * SPAD;  ar += 32;  ph += 32;  pl += 32;
        }
    }
}

// ---------------------------------------------------------------------------
// Kernel 4: out = P @ v via bf16 split mma.sync (hi*hi + hi*lo + lo*hi).
// CTA tile: 128 M x 64 N, K = 2048. 8 warps = 4 (wm) x 2 (wn); warp tile
// m32 x n32 = 2 m16 x 4 n8 mma tiles. A/B fragments loaded directly (LDG.32).
// ---------------------------------------------------------------------------
__global__ __launch_bounds__(256)
void gemm_kernel(float* __restrict__ out) {   // [H, L, DK]
    int tid = threadIdx.x, lane = tid & 31, w = tid >> 5;
    int head = blockIdx.x >> 4;
    int row0 = (blockIdx.x & 15) << 7;
    int wm = w >> 1, wn = w & 1;
    int g = lane >> 2, tq = lane & 3;

    const __nv_bfloat16* Ph = g_Phi + ((size_t)(head * L) + row0) * L;
    const __nv_bfloat16* Pl = g_Plo + ((size_t)(head * L) + row0) * L;

    const __nv_bfloat16 *pAh[2][2], *pAl[2][2];
#pragma unroll
    for (int mi = 0; mi < 2; mi++) {
        int r = wm * 32 + mi * 16 + g;
        pAh[mi][0] = Ph + (size_t)r * L;        pAh[mi][1] = Ph + (size_t)(r + 8) * L;
        pAl[mi][0] = Pl + (size_t)r * L;        pAl[mi][1] = Pl + (size_t)(r + 8) * L;
    }
    const __nv_bfloat16 *pBh[4], *pBl[4];
#pragma unroll
    for (int ni = 0; ni < 4; ni++) {
        int n = wn * 32 + ni * 8 + g;
        pBh[ni] = g_Vthi + ((size_t)head * DK + n) * L;
        pBl[ni] = g_Vtlo + ((size_t)head * DK + n) * L;
    }

    float acc[2][4][4];
#pragma unroll
    for (int mi = 0; mi < 2; mi++)
#pragma unroll
        for (int ni = 0; ni < 4; ni++)
#pragma unroll
            for (int e = 0; e < 4; e++) acc[mi][ni][e] = 0.f;

    for (int k0 = 0; k0 < L; k0 += 16) {
        int c0 = k0 + 2 * tq;
        unsigned ah[2][4], al[2][4], bh[4][2], bl[4][2];
#pragma unroll
        for (int mi = 0; mi < 2; mi++) {
            ah[mi][0] = *(const unsigned*)(pAh[mi][0] + c0);
            ah[mi][1] = *(const unsigned*)(pAh[mi][1] + c0);
            ah[mi][2] = *(const unsigned*)(pAh[mi][0] + c0 + 8);
            ah[mi][3] = *(const unsigned*)(pAh[mi][1] + c0 + 8);
            al[mi][0] = *(const unsigned*)(pAl[mi][0] + c0);
            al[mi][1] = *(const unsigned*)(pAl[mi][1] + c0);
            al[mi][2] = *(const unsigned*)(pAl[mi][0] + c0 + 8);
            al[mi][3] = *(const unsigned*)(pAl[mi][1] + c0 + 8);
        }
#pragma unroll
        for (int ni = 0; ni < 4; ni++) {
            bh[ni][0] = *(const unsigned*)(pBh[ni] + c0);
            bh[ni][1] = *(const unsigned*)(pBh[ni] + c0 + 8);
            bl[ni][0] = *(const unsigned*)(pBl[ni] + c0);
            bl[ni][1] = *(const unsigned*)(pBl[ni] + c0 + 8);
        }
#pragma unroll
        for (int mi = 0; mi < 2; mi++)
#pragma unroll
            for (int ni = 0; ni < 4; ni++) {
                MMA16816(acc[mi][ni], ah[mi], bh[ni]);
                MMA16816(acc[mi][ni], ah[mi], bl[ni]);
                MMA16816(acc[mi][ni], al[mi], bh[ni]);
            }
    }

    float* op = out + ((size_t)(head * L) + row0) * DK;
#pragma unroll
    for (int mi = 0; mi < 2; mi++) {
        int r0 = wm * 32 + mi * 16 + g;
#pragma unroll
        for (int ni = 0; ni < 4; ni++) {
            int n0 = wn * 32 + ni * 8 + 2 * tq;
            *(float2*)(op + (size_t)r0 * DK + n0) =
                make_float2(acc[mi][ni][0], acc[mi][ni][1]);
            *(float2*)(op + (size_t)(r0 + 8) * DK + n0) =
                make_float2(acc[mi][ni][2], acc[mi][ni][3]);
        }
    }
}

// ---------------------------------------------------------------------------
extern "C" void kernel_launch(void* const* d_in, const int* in_sizes, int n_in,
                              void* d_out, int out_size) {
    const float* q  = (const float*)d_in[0];
    const float* v  = (const float*)d_in[1];
    const float* Wa = (const float*)d_in[2];
    const float* ba = (const float*)d_in[3];
    const float* Wb = (const float*)d_in[4];
    const float* bb = (const float*)d_in[5];

    float* out  = (float*)d_out;                 // [H, L, DK]
    float* attn = out + (size_t)H * L * DK;      // [H, L, L]

    const int smem = (L * SPAD + ROWS * RB + 2 * 8192) * 4;   // 231424 B
    cudaFuncSetAttribute(attn_kernel, cudaFuncAttributeMaxDynamicSharedMemorySize, smem);

    proj_kernel<<<H * L / 64, 256>>>(q, Wa, ba, Wb, bb);
    vsplit_kernel<<<H * (L / 64), 256>>>(v);
    attn_kernel<<<H * (L / ROWS), 512, smem>>>(attn);
    gemm_kernel<<<H * (L / 128), 256>>>(out);
}

// round 17
// speedup vs baseline: 1.3834x; 1.3834x over previous
#include <cuda_runtime.h>
#include <cuda_bf16.h>
#include <math.h>

#define H    16
#define L    2048
#define DK   64
#define RB   32
#define ROWS 16
#define SPAD 20          // padded row of S[j][.] in floats (16 data + 4 pad)

// Scratch (device globals: no allocs allowed)
__device__ float g_C[H * L * RB];
__device__ float g_B[H * L * RB];
__device__ __nv_bfloat16 g_Vthi[(size_t)H * DK * L]; // v transposed [d][j], hi
__device__ __nv_bfloat16 g_Vtlo[(size_t)H * DK * L]; // v transposed [d][j], lo

// ---- helpers ----------------------------------------------------------------
typedef unsigned long long u64;
typedef unsigned u32;

__device__ __forceinline__ void fma2(u64 &acc, u64 a, u64 b) {
    asm("fma.rn.f32x2 %0, %1, %2, %0;" : "+l"(acc) : "l"(a), "l"(b));
}
__device__ __forceinline__ float2 upk(u64 v) {
    float2 r; asm("mov.b64 {%0, %1}, %2;" : "=f"(r.x), "=f"(r.y) : "l"(v)); return r;
}
__device__ __forceinline__ void cp16(float* dst_smem, const float* src) {
    u32 s = (u32)__cvta_generic_to_shared(dst_smem);
    asm volatile("cp.async.cg.shared.global [%0], [%1], 16;" :: "r"(s), "l"(src));
}
__device__ __forceinline__ void cp16b(char* dst_smem, const void* src) {
    u32 s = (u32)__cvta_generic_to_shared(dst_smem);
    asm volatile("cp.async.cg.shared.global [%0], [%1], 16;" :: "r"(s), "l"(src));
}
__device__ __forceinline__ void cp_commit() { asm volatile("cp.async.commit_group;"); }
__device__ __forceinline__ void cp_wait0()  { asm volatile("cp.async.wait_group 0;"); }

// pack two fp32 -> bf16x2 (low = lo_elem = element k, high = hi_elem = element k+1)
__device__ __forceinline__ u32 pkbf(float hi_elem, float lo_elem) {
    u32 r; asm("cvt.rn.bf16x2.f32 %0, %1, %2;" : "=r"(r) : "f"(hi_elem), "f"(lo_elem));
    return r;
}
// unpack bf16x2 to the two fp32 values (x = low elem, y = high elem)
__device__ __forceinline__ float2 bf2f(u32 h) {
    float2 f;
    f.x = __uint_as_float(h << 16);
    f.y = __uint_as_float(h & 0xffff0000u);
    return f;
}
__device__ __forceinline__ void ldsm2(u32 &r0, u32 &r1, u32 addr) {
    asm volatile("ldmatrix.sync.aligned.m8n8.x2.shared.b16 {%0,%1}, [%2];"
                 : "=r"(r0), "=r"(r1) : "r"(addr));
}

#define MMA16816(D, A, B)                                                     \
    asm volatile("mma.sync.aligned.m16n8k16.row.col.f32.bf16.bf16.f32 "       \
                 "{%0,%1,%2,%3}, {%4,%5,%6,%7}, {%8,%9}, {%0,%1,%2,%3};"      \
                 : "+f"((D)[0]), "+f"((D)[1]), "+f"((D)[2]), "+f"((D)[3])     \
                 : "r"((A)[0]), "r"((A)[1]), "r"((A)[2]), "r"((A)[3]),        \
                   "r"((B)[0]), "r"((B)[1]))

// ---------------------------------------------------------------------------
// Kernel 1: projections (unchanged).
// ---------------------------------------------------------------------------
__global__ __launch_bounds__(256)
void proj_kernel(const float* __restrict__ q,
                 const float* __restrict__ Wa, const float* __restrict__ ba,
                 const float* __restrict__ Wb, const float* __restrict__ bb) {
    __shared__ float Ut[DK * DK];   // [k][o]
    __shared__ float us[DK];
    __shared__ float qs[64 * DK];   // [r][k]
    int tid = threadIdx.x;
    int row0 = blockIdx.x * 64;

    for (int i = tid; i < DK * DK; i += 256) {
        int o = i >> 6, k = i & 63;
        float u;
        if (o < 32) u = 32.f * (Wa[(2 * o) * DK + k] + Wa[(2 * o + 1) * DK + k]);
        else        u = Wb[(o - 32) * DK + k];
        Ut[k * DK + o] = u;
    }
    if (tid < DK)
        us[tid] = (tid < 32) ? 32.f * (ba[2 * tid] + ba[2 * tid + 1]) : bb[tid - 32];
    {
        float4* q4 = (float4*)qs;  const float4* g4 = (const float4*)(q + (size_t)row0 * DK);
        for (int i = tid; i < 64 * DK / 4; i += 256) q4[i] = g4[i];
    }
    __syncthreads();

    int tr = tid >> 4, tc = tid & 15;
    float acc[4][4] = {};
#pragma unroll 8
    for (int k = 0; k < DK; k++) {
        float4 u = *(const float4*)(Ut + k * DK + 4 * tc);
        float qv[4];
#pragma unroll
        for (int ri = 0; ri < 4; ri++) qv[ri] = qs[(4 * tr + ri) * DK + k];
#pragma unroll
        for (int ri = 0; ri < 4; ri++) {
            acc[ri][0] += qv[ri] * u.x;  acc[ri][1] += qv[ri] * u.y;
            acc[ri][2] += qv[ri] * u.z;  acc[ri][3] += qv[ri] * u.w;
        }
    }
    float4 ub = *(const float4*)(us + 4 * tc);
#pragma unroll
    for (int ri = 0; ri < 4; ri++) {
        int row = row0 + 4 * tr + ri;
        float4 o = make_float4(acc[ri][0] + ub.x, acc[ri][1] + ub.y,
                               acc[ri][2] + ub.z, acc[ri][3] + ub.w);
        if (tc < 8) *(float4*)(g_C + (size_t)row * RB + 4 * tc)        = o;
        else        *(float4*)(g_B + (size_t)row * RB + (4 * tc - 32)) = o;
    }
}

// ---------------------------------------------------------------------------
// Kernel 2: v transpose + bf16 split.  Vt_hi/lo[head][d][j].
// ---------------------------------------------------------------------------
__global__ __launch_bounds__(256)
void vsplit_kernel(const float* __restrict__ v) {
    __shared__ float ts[64][65];
    int tid = threadIdx.x;
    int head = blockIdx.x >> 5;          // L/64 = 32 tiles per head
    int j0 = (blockIdx.x & 31) * 64;
    const float* gv = v + ((size_t)head * L + j0) * DK;
#pragma unroll
    for (int i = tid; i < 64 * 64; i += 256) {
        int jj = i >> 6, d = i & 63;
        ts[jj][d] = gv[jj * DK + d];
    }
    __syncthreads();
#pragma unroll
    for (int i = tid; i < 64 * 64; i += 256) {
        int d = i >> 6, jj = i & 63;
        float val = ts[jj][d];
        __nv_bfloat16 hi = __float2bfloat16(val);
        __nv_bfloat16 lo = __float2bfloat16(val - __bfloat162float(hi));
        size_t idx = ((size_t)head * DK + d) * L + j0 + jj;
        g_Vthi[idx] = hi;
        g_Vtlo[idx] = lo;
    }
}

// ---------------------------------------------------------------------------
// Kernel 3: fused S + softmax + tensor-core E@v.
//  Phase 1: S = C @ B^T (double-buffered cp.async, f32x2) — as R11.
//  Phase 2: 3-pass softmax; attn = E*inv written out; E kept in S.
//  Phase 3: out = (E @ v) * inv via split-bf16 mma.sync.m16n8k16:
//           A from S (scalar LDS + cvt split), B from smem-staged Vt chunks
//           (cp.async, XOR-swizzled, ldmatrix.x2). Warp = (k-slice, n-half).
//           Cross-warp fp32 reduction in dead S region.
// ---------------------------------------------------------------------------
__global__ __launch_bounds__(512, 1)
void attn_kernel(float* __restrict__ out,    // [H, L, DK]
                 float* __restrict__ attn) { // [H, L, L]
    extern __shared__ float sm[];
    float* S   = sm;                  // L * SPAD  = 40960 floats
    float* Cs  = S + L * SPAD;        // ROWS * RB = 512
    float* buf = Cs + ROWS * RB;      // 16384 floats = 64 KB staging region

    int tid  = threadIdx.x;
    int lane = tid & 31, w = tid >> 5;
    int head = blockIdx.x >> 7;
    int rt   = blockIdx.x & 127;
    int row0 = rt * ROWS;

    const float* gB = g_B + (size_t)head * L * RB;

    // stage B chunk 0
    {
#pragma unroll
        for (int t = 0; t < 4; t++) {
            int idx4 = tid + 512 * t;              // float4 index, 0..2047
            int j = idx4 >> 3, i = idx4 & 7;
            cp16(buf + j * RB + 4 * (i ^ (j & 7)), gB + (size_t)j * RB + 4 * i);
        }
        cp_commit();
    }

    // C tile for these 16 rows
    {
        const float4* c4 = (const float4*)(g_C + (size_t)(head * L + row0) * RB);
        float4* d4 = (float4*)Cs;
        for (int i = tid; i < ROWS * RB / 4; i += 512) d4[i] = c4[i];
    }

    // ---- Phase 1: S[j][r] = sum_m C[r][m] * B[j][m] --------------------------
    int jq = tid & 127, rq = tid >> 7;        // 2 j per thread, 4-row quad rq
    for (int c = 0; c < 8; c++) {
        cp_wait0();
        __syncthreads();
        if (c < 7) {
            float* bn = buf + ((c + 1) & 1) * 8192;
            const float* gn = gB + (size_t)(c + 1) * 256 * RB;
#pragma unroll
            for (int t = 0; t < 4; t++) {
                int idx4 = tid + 512 * t;
                int j = idx4 >> 3, i = idx4 & 7;
                cp16(bn + j * RB + 4 * (i ^ (j & 7)), gn + (size_t)j * RB + 4 * i);
            }
            cp_commit();
        }
        const float* bc = buf + (c & 1) * 8192;
        int j0 = c * 256;
        int jA = jq, jB = jq + 128;
        u64 acc[2][4];
#pragma unroll
        for (int a = 0; a < 2; a++)
#pragma unroll
            for (int b = 0; b < 4; b++) acc[a][b] = 0ull;
#pragma unroll
        for (int i = 0; i < 8; i++) {
            ulonglong2 c0 = *(const ulonglong2*)(Cs + (4 * rq + 0) * RB + 4 * i);
            ulonglong2 c1 = *(const ulonglong2*)(Cs + (4 * rq + 1) * RB + 4 * i);
            ulonglong2 c2 = *(const ulonglong2*)(Cs + (4 * rq + 2) * RB + 4 * i);
            ulonglong2 c3 = *(const ulonglong2*)(Cs + (4 * rq + 3) * RB + 4 * i);
            ulonglong2 bA = *(const ulonglong2*)(bc + jA * RB + 4 * (i ^ (jA & 7)));
            ulonglong2 bB = *(const ulonglong2*)(bc + jB * RB + 4 * (i ^ (jB & 7)));
            fma2(acc[0][0], c0.x, bA.x);  fma2(acc[0][0], c0.y, bA.y);
            fma2(acc[0][1], c1.x, bA.x);  fma2(acc[0][1], c1.y, bA.y);
            fma2(acc[0][2], c2.x, bA.x);  fma2(acc[0][2], c2.y, bA.y);
            fma2(acc[0][3], c3.x, bA.x);  fma2(acc[0][3], c3.y, bA.y);
            fma2(acc[1][0], c0.x, bB.x);  fma2(acc[1][0], c0.y, bB.y);
            fma2(acc[1][1], c1.x, bB.x);  fma2(acc[1][1], c1.y, bB.y);
            fma2(acc[1][2], c2.x, bB.x);  fma2(acc[1][2], c2.y, bB.y);
            fma2(acc[1][3], c3.x, bB.x);  fma2(acc[1][3], c3.y, bB.y);
        }
        {
            float2 t0 = upk(acc[0][0]), t1 = upk(acc[0][1]),
                   t2 = upk(acc[0][2]), t3 = upk(acc[0][3]);
            int key = (jA >> 3) & 1;
            *(float4*)(S + (size_t)(j0 + jA) * SPAD + 4 * (rq ^ key)) =
                make_float4(t0.x + t0.y, t1.x + t1.y, t2.x + t2.y, t3.x + t3.y);
        }
        {
            float2 t0 = upk(acc[1][0]), t1 = upk(acc[1][1]),
                   t2 = upk(acc[1][2]), t3 = upk(acc[1][3]);
            int key = (jB >> 3) & 1;
            *(float4*)(S + (size_t)(j0 + jB) * SPAD + 4 * (rq ^ key)) =
                make_float4(t0.x + t0.y, t1.x + t1.y, t2.x + t2.y, t3.x + t3.y);
        }
    }

    // Issue Vt chunk-0 staging now (overlaps softmax). buf half 0 is free:
    // last Phase-1 compute used half 1, and the c=7 barrier drained half 0 readers.
    char* smc = (char*)sm;
    unsigned bufByte = (unsigned)((char*)buf - smc);
    const __nv_bfloat16* Vh = g_Vthi + (size_t)head * DK * L;
    const __nv_bfloat16* Vl = g_Vtlo + (size_t)head * DK * L;
    {
#pragma unroll
        for (int t = 0; t < 4; t++) {
            int idx = tid + 512 * t;               // 0..2047 16B units
            int sel = idx >> 10;                    // 0 = hi, 1 = lo
            int k = idx & 1023;
            int d = k >> 4, u = k & 15;
            char* dst = smc + bufByte + sel * 16384 + d * 256 + ((u ^ (d & 7)) * 16);
            const __nv_bfloat16* src = (sel ? Vl : Vh) + (size_t)d * L + u * 8;
            cp16b(dst, src);
        }
        cp_commit();
    }
    __syncthreads();

    // ---- Phase 2: softmax, warp w owns row w; attn = E*inv; E stays in S ----
    {
        int r = w, g = r >> 2, e = r & 3;
        int off = 4 * (g ^ ((lane >> 3) & 1)) + e;
        const float* p0 = S + lane * SPAD + off;
        float mx = -1e30f;
#pragma unroll
        for (int k = 0; k < 64; k++) { mx = fmaxf(mx, *p0); p0 += 32 * SPAD; }
#pragma unroll
        for (int o = 16; o > 0; o >>= 1) mx = fmaxf(mx, __shfl_xor_sync(0xffffffffu, mx, o));
        float* p1 = S + lane * SPAD + off;
        float sum = 0.f;
#pragma unroll
        for (int k = 0; k < 64; k++) {
            float ee = __expf(*p1 - mx);
            *p1 = ee;
            sum += ee;
            p1 += 32 * SPAD;
        }
#pragma unroll
        for (int o = 16; o > 0; o >>= 1) sum += __shfl_xor_sync(0xffffffffu, sum, o);
        float inv = 1.f / sum;
        if (lane == 0) Cs[r] = inv;
        const float* p2 = S + lane * SPAD + off;
        float* ar = attn + (size_t)(head * L + row0 + r) * L + lane;
#pragma unroll
        for (int k = 0; k < 64; k++) {
            *ar = *p2 * inv;
            p2 += 32 * SPAD;  ar += 32;
        }
    }
    __syncthreads();

    // ---- Phase 3: out = E @ v via split-bf16 mma -----------------------------
    int sw = w & 7, nh = w >> 3;          // k-slice (8), n-half (2)
    int g3 = lane >> 2, tq = lane & 3;
    // A-fragment S offsets (r = g3 / g3+8; key 0 for j in first 8, 1 for +8)
    int off0  = 4 * ((g3 >> 2))       + (g3 & 3);
    int off0k = 4 * ((g3 >> 2) ^ 1)   + (g3 & 3);
    int off8  = 4 * (2 + (g3 >> 2))       + (g3 & 3);
    int off8k = 4 * ((2 + (g3 >> 2)) ^ 1) + (g3 & 3);
    // B ldmatrix per-thread base (byte offset inside a buffer half)
    unsigned rowB = lane & 7;
    unsigned msel = (lane >> 3) & 1;
    u32 smem_base = (u32)__cvta_generic_to_shared(sm);
    unsigned bOff = rowB * 256 + (((unsigned)(sw * 2) + msel) ^ rowB) * 16;

    float accD[4][4];
#pragma unroll
    for (int ni = 0; ni < 4; ni++)
#pragma unroll
        for (int e = 0; e < 4; e++) accD[ni][e] = 0.f;

    for (int c = 0; c < 16; c++) {
        cp_wait0();
        __syncthreads();                  // Vt chunk c visible; other half free
        if (c < 15) {
            int hb = (c + 1) & 1;
            int j0n = (c + 1) * 128;
#pragma unroll
            for (int t = 0; t < 4; t++) {
                int idx = tid + 512 * t;
                int sel = idx >> 10;
                int k = idx & 1023;
                int d = k >> 4, u = k & 15;
                char* dst = smc + bufByte + hb * 32768 + sel * 16384
                          + d * 256 + ((u ^ (d & 7)) * 16);
                const __nv_bfloat16* src = (sel ? Vl : Vh) + (size_t)d * L + j0n + u * 8;
                cp16b(dst, src);
            }
            cp_commit();
        }
        // A fragments from S (fp32 -> bf16 hi/lo)
        const float* Sj = S + (size_t)(c * 128 + sw * 16 + 2 * tq) * SPAD;
        float x0 = Sj[off0],            x1 = Sj[SPAD + off0];
        float x8 = Sj[8 * SPAD + off0k], x9 = Sj[9 * SPAD + off0k];
        float y0 = Sj[off8],            y1 = Sj[SPAD + off8];
        float y8 = Sj[8 * SPAD + off8k], y9 = Sj[9 * SPAD + off8k];
        u32 ah[4], al[4];
        ah[0] = pkbf(x1, x0); { float2 f = bf2f(ah[0]); al[0] = pkbf(x1 - f.y, x0 - f.x); }
        ah[1] = pkbf(y1, y0); { float2 f = bf2f(ah[1]); al[1] = pkbf(y1 - f.y, y0 - f.x); }
        ah[2] = pkbf(x9, x8); { float2 f = bf2f(ah[2]); al[2] = pkbf(x9 - f.y, x8 - f.x); }
        ah[3] = pkbf(y9, y8); { float2 f = bf2f(ah[3]); al[3] = pkbf(y9 - f.y, y8 - f.x); }

        unsigned hbase = smem_base + bufByte + (unsigned)(c & 1) * 32768 + bOff
                       + nh * 8192;
#pragma unroll
        for (int ni = 0; ni < 4; ni++) {
            u32 bh[2], bl[2];
            ldsm2(bh[0], bh[1], hbase + ni * 2048);
            ldsm2(bl[0], bl[1], hbase + ni * 2048 + 16384);
            MMA16816(accD[ni], ah, bh);
            MMA16816(accD[ni], ah, bl);
            MMA16816(accD[ni], al, bh);
        }
    }

    // ---- Epilogue: 16-part reduction in dead S (stride 33, conflict-free) ---
    __syncthreads();                      // all MMA A-reads from S complete
    {
        float* red = S;                   // red[p*528 + r*33 + nl], nl in 0..31
#pragma unroll
        for (int ni = 0; ni < 4; ni++) {
            int nl = ni * 8 + 2 * tq;
            red[w * 528 + g3 * 33 + nl]           = accD[ni][0];
            red[w * 528 + g3 * 33 + nl + 1]       = accD[ni][1];
            red[w * 528 + (g3 + 8) * 33 + nl]     = accD[ni][2];
            red[w * 528 + (g3 + 8) * 33 + nl + 1] = accD[ni][3];
        }
        __syncthreads();
#pragma unroll
        for (int t = 0; t < 2; t++) {
            int idx = tid + 512 * t;           // 1024 outputs = 16 r x 64 n
            int r = idx >> 6, n = idx & 63;
            int nh2 = n >> 5, nl = n & 31;
            float s = 0.f;
            const float* rp = red + (nh2 * 8) * 528 + r * 33 + nl;
#pragma unroll
            for (int swi = 0; swi < 8; swi++) { s += *rp; rp += 528; }
            out[(size_t)(head * L + row0 + r) * DK + n] = s * Cs[r];
        }
    }
}

// ---------------------------------------------------------------------------
extern "C" void kernel_launch(void* const* d_in, const int* in_sizes, int n_in,
                              void* d_out, int out_size) {
    const float* q  = (const float*)d_in[0];
    const float* v  = (const float*)d_in[1];
    const float* Wa = (const float*)d_in[2];
    const float* ba = (const float*)d_in[3];
    const float* Wb = (const float*)d_in[4];
    const float* bb = (const float*)d_in[5];

    float* out  = (float*)d_out;                 // [H, L, DK]
    float* attn = out + (size_t)H * L * DK;      // [H, L, L]

    const int smem = (L * SPAD + ROWS * RB + 2 * 8192) * 4;   // 231424 B
    cudaFuncSetAttribute(attn_kernel, cudaFuncAttributeMaxDynamicSharedMemorySize, smem);

    proj_kernel<<<H * L / 64, 256>>>(q, Wa, ba, Wb, bb);
    vsplit_kernel<<<H * (L / 64), 256>>>(v);
    attn_kernel<<<H * (L / ROWS), 512, smem>>>(out, attn);
}